// round 16
// baseline (speedup 1.0000x reference)
#include <cuda_runtime.h>
#include <stdint.h>

#define BB 512
#define SS 1024
#define TT 48

__device__ float g_partial[BB];

__device__ __forceinline__ unsigned long long pk2(float x, float y) {
    unsigned long long r;
    asm("mov.b64 %0, {%1,%2};" : "=l"(r) : "f"(x), "f"(y));
    return r;
}
__device__ __forceinline__ void upk2(unsigned long long v, float& x, float& y) {
    asm("mov.b64 {%0,%1}, %2;" : "=f"(x), "=f"(y) : "l"(v));
}
__device__ __forceinline__ unsigned long long fma2(unsigned long long a, unsigned long long b, unsigned long long c) {
    unsigned long long d;
    asm("fma.rn.f32x2 %0, %1, %2, %3;" : "=l"(d) : "l"(a), "l"(b), "l"(c));
    return d;
}
__device__ __forceinline__ unsigned long long add2(unsigned long long a, unsigned long long b) {
    unsigned long long d;
    asm("add.rn.f32x2 %0, %1, %2;" : "=l"(d) : "l"(a), "l"(b));
    return d;
}

// One warp per sequence, 4 warps/CTA (one per SMSP), 128 CTAs (1/SM).
// R10 structure (proven 123.4us): lane l owns col l (pA, 24 FMA2) and col
// 32+(l&15) (pB, 24 FMA2, duplicated across half-warps -- the price of ZERO
// cross-lane communication in the loop). This round: quad-cadence rescale +
// clamp-free prefetch in the main region. No other changes.
__global__ __launch_bounds__(128, 1) void crf_main(
    const float* __restrict__ em,          // [B,S,T]
    const int* __restrict__ tags,          // [B,S]
    const unsigned char* __restrict__ mask,// [B,S] bool OR int32 (auto-detected)
    const float* __restrict__ startT,      // [T]
    const float* __restrict__ endT,        // [T]
    const float* __restrict__ trans)       // [T,T]
{
    __shared__ __align__(16) float sP[4][2][TT];

    const unsigned FULL = 0xffffffffu;
    int tid = threadIdx.x;
    int w   = tid >> 5;
    int l   = tid & 31;
    int b   = blockIdx.x * 4 + w;

    bool isbool = ((mask[1] | mask[1025] | mask[2049] | mask[3073]) != 0);

    const float* embT = em + (size_t)b * SS * TT;
    const int*   tgT  = tags + (size_t)b * SS;

    // ===== parallel prologue: gold-path numerator + length (32 t's/lane) ====
    float num = 0.f;
    int cnt = 0;
    #pragma unroll 4
    for (int k = 0; k < 32; k++) {
        int t = l + 32 * k;
        int mk = isbool ? (int)mask[(size_t)b * SS + t]
                        : ((const int*)mask)[(size_t)b * SS + t];
        int tg = tgT[t];
        if (t == 0) {
            num += startT[tg] + embT[tg];
        } else {
            int tgm = tgT[t - 1];
            float cval = trans[tgm * TT + tg] + embT[t * TT + tg];
            num += mk ? cval : 0.f;
        }
        cnt += mk ? 1 : 0;
    }
    #pragma unroll
    for (int o = 16; o; o >>= 1) {
        num += __shfl_xor_sync(FULL, num, o);
        cnt += __shfl_xor_sync(FULL, cnt, o);
    }
    int len = cnt;
    if (len < 1) len = 1;
    if (len > SS) len = SS;
    num += endT[tgT[len - 1]];           // uniform across lanes

    // ===== this lane's two output columns =====
    int jA = l;
    int jB = 32 + (l & 15);

    // ===== E = exp(transitions) columns in registers (f32x2 pairs) =====
    unsigned long long colA[24], colB[24];
    #pragma unroll
    for (int m = 0; m < 24; m++) {
        colA[m] = pk2(__expf(trans[(2 * m) * TT + jA]),
                      __expf(trans[(2 * m + 1) * TT + jA]));
        colB[m] = pk2(__expf(trans[(2 * m) * TT + jB]),
                      __expf(trans[(2 * m + 1) * TT + jB]));
    }

    // ===== init p0 = exp(start + emit0 - shift) =====
    float sA0 = startT[jA] + embT[jA];
    float sB0 = startT[jB] + embT[jB];
    float shift = __shfl_sync(FULL, sA0, 0);
    sP[w][0][l] = __expf(sA0 - shift);
    if (l < 16) sP[w][0][32 + l] = __expf(sB0 - shift);
    __syncwarp();

    // ===== emission prefetch ring (depth 4); row r at slot (r-1)&3 =====
    float bufA[4], bufB[4];
    #pragma unroll
    for (int u = 0; u < 4; u++) {
        bufA[u] = embT[(1 + u) * TT + jA];
        bufB[u] = embT[(1 + u) * TT + jB];
    }

    int ksum = 0;

    // ---- one recurrence step (branchless; RESC/CLAMP are literal 0/1) ----
    #define CRF_STEP(t, idx, RESC, CLAMP)                                      \
    {                                                                          \
        float wA = __expf(bufA[idx]);                                          \
        float wB = __expf(bufB[idx]);                                          \
        int tp = (t) + 4;                                                      \
        if (CLAMP) { if (tp > SS - 1) tp = SS - 1; }                           \
        bufA[idx] = embT[tp * TT + jA];                                        \
        bufB[idx] = embT[tp * TT + jB];                                        \
        int rb = ((t) + 1) & 1, wb = (t) & 1;                                  \
        const ulonglong2* sp =                                                 \
            reinterpret_cast<const ulonglong2*>(&sP[w][rb][0]);                \
        ulonglong2 v0 = sp[0];                                                 \
        if (RESC) {                                                            \
            float p00, p01;                                                    \
            upk2(v0.x, p00, p01);                                              \
            unsigned eb = (__float_as_uint(p00) >> 23) & 255u;                 \
            if (eb < 64u) eb = 64u;                                            \
            if (eb > 190u) eb = 190u;                                          \
            int kk = (int)eb - 127;                                            \
            float Mf = __uint_as_float((unsigned)(127 - kk) << 23);            \
            ksum += kk;                                                        \
            wA *= Mf; wB *= Mf;                                                \
        }                                                                      \
        unsigned long long a0 = 0, a1 = 0, c0 = 0, c1 = 0;                     \
        a0 = fma2(v0.x, colA[0], a0);                                          \
        c0 = fma2(v0.x, colB[0], c0);                                          \
        a1 = fma2(v0.y, colA[1], a1);                                          \
        c1 = fma2(v0.y, colB[1], c1);                                          \
        _Pragma("unroll")                                                      \
        for (int q = 1; q < 12; q++) {                                         \
            ulonglong2 v = sp[q];                                              \
            a0 = fma2(v.x, colA[2 * q], a0);                                   \
            c0 = fma2(v.x, colB[2 * q], c0);                                   \
            a1 = fma2(v.y, colA[2 * q + 1], a1);                               \
            c1 = fma2(v.y, colB[2 * q + 1], c1);                               \
        }                                                                      \
        float xA, yA, xB, yB;                                                  \
        upk2(add2(a0, a1), xA, yA);                                            \
        upk2(add2(c0, c1), xB, yB);                                            \
        float pA = (xA + yA) * wA;                                             \
        float pB = (xB + yB) * wB;                                             \
        sP[w][wb][l] = pA;                                                     \
        if (l < 16) sP[w][wb][32 + l] = pB;                                    \
        __syncwarp();                                                          \
    }

    int t = 1;
    // main region: no prefetch clamp needed (t+7 <= SS-1), rescale at quad head
    int tsafe = (len < SS - 7) ? len : (SS - 7);
    for (; t + 3 < tsafe; t += 4) {
        CRF_STEP(t + 0, 0, 1, 0)
        CRF_STEP(t + 1, 1, 0, 0)
        CRF_STEP(t + 2, 2, 0, 0)
        CRF_STEP(t + 3, 3, 0, 0)
    }
    // late quads: clamped prefetch
    for (; t + 3 < len; t += 4) {
        CRF_STEP(t + 0, 0, 1, 1)
        CRF_STEP(t + 1, 1, 0, 1)
        CRF_STEP(t + 2, 2, 0, 1)
        CRF_STEP(t + 3, 3, 0, 1)
    }
    // remainder (0-3 steps): rescale every step (cheap, always safe)
    for (; t < len; t++) {
        int idx = (t - 1) & 3;
        CRF_STEP(t, idx, 1, 1)
    }
    #undef CRF_STEP

    // ===== finalize: logZ = log(sum_j p_j e^{end_j}) + shift + ksum*ln2 =====
    int fb = (len - 1) & 1;
    float fin = sP[w][fb][jA] * __expf(endT[jA]);
    if (l < 16) fin += sP[w][fb][jB] * __expf(endT[jB]);
    #pragma unroll
    for (int o = 16; o; o >>= 1) fin += __shfl_xor_sync(FULL, fin, o);
    if (l == 0) {
        float logZ = __logf(fin) + shift + (float)ksum * 0.69314718055994531f;
        g_partial[b] = logZ - num;
    }
}

__global__ void crf_reduce(float* __restrict__ out) {
    __shared__ float s[256];
    int tid = threadIdx.x;
    s[tid] = g_partial[tid] + g_partial[tid + 256];
    __syncthreads();
    #pragma unroll
    for (int o = 128; o > 0; o >>= 1) {
        if (tid < o) s[tid] += s[tid + o];
        __syncthreads();
    }
    if (tid == 0) out[0] = s[0] * (1.0f / (float)BB);
}

extern "C" void kernel_launch(void* const* d_in, const int* in_sizes, int n_in,
                              void* d_out, int out_size) {
    const float*         em   = (const float*)d_in[0];
    const int*           tags = (const int*)d_in[1];
    const unsigned char* mask = (const unsigned char*)d_in[2];
    const float*         st   = (const float*)d_in[3];
    const float*         en   = (const float*)d_in[4];
    const float*         tr   = (const float*)d_in[5];
    crf_main<<<BB / 4, 128>>>(em, tags, mask, st, en, tr);
    crf_reduce<<<1, 256>>>((float*)d_out);
}

// round 17
// speedup vs baseline: 1.5768x; 1.5768x over previous
#include <cuda_runtime.h>
#include <stdint.h>

#define BB 512
#define SS 1024
#define TT 48

__device__ float g_partial[BB];
__device__ int   g_ctr;          // zero-init; reset by last CTA each run

__device__ __forceinline__ unsigned long long pk2(float x, float y) {
    unsigned long long r;
    asm("mov.b64 %0, {%1,%2};" : "=l"(r) : "f"(x), "f"(y));
    return r;
}
__device__ __forceinline__ void upk2(unsigned long long v, float& x, float& y) {
    asm("mov.b64 {%0,%1}, %2;" : "=f"(x), "=f"(y) : "l"(v));
}
__device__ __forceinline__ unsigned long long fma2(unsigned long long a, unsigned long long b, unsigned long long c) {
    unsigned long long d;
    asm("fma.rn.f32x2 %0, %1, %2, %3;" : "=l"(d) : "l"(a), "l"(b), "l"(c));
    return d;
}
__device__ __forceinline__ unsigned long long add2(unsigned long long a, unsigned long long b) {
    unsigned long long d;
    asm("add.rn.f32x2 %0, %1, %2;" : "=l"(d) : "l"(a), "l"(b));
    return d;
}

// One warp per sequence, 4 warps/CTA (one per SMSP), 128 CTAs (1/SM).
// Exact R10 loop structure (proven 123.4us). Diffs vs R10 (shrink-only):
//  - rescale only at quad head (RESC literal): bodies 2-4 lose ~8 instrs
//  - final mean fused via last-CTA reduction (second launch removed)
__global__ __launch_bounds__(128, 1) void crf_main(
    const float* __restrict__ em,          // [B,S,T]
    const int* __restrict__ tags,          // [B,S]
    const unsigned char* __restrict__ mask,// [B,S] bool OR int32 (auto-detected)
    const float* __restrict__ startT,      // [T]
    const float* __restrict__ endT,        // [T]
    const float* __restrict__ trans,       // [T,T]
    float* __restrict__ out)               // [1]
{
    __shared__ __align__(16) float sP[4][2][TT];
    __shared__ float sRed[128];
    __shared__ int   sLast;

    const unsigned FULL = 0xffffffffu;
    int tid = threadIdx.x;
    int w   = tid >> 5;
    int l   = tid & 31;
    int b   = blockIdx.x * 4 + w;

    bool isbool = ((mask[1] | mask[1025] | mask[2049] | mask[3073]) != 0);

    const float* embT = em + (size_t)b * SS * TT;
    const int*   tgT  = tags + (size_t)b * SS;

    // ===== parallel prologue: gold-path numerator + length (32 t's/lane) ====
    float num = 0.f;
    int cnt = 0;
    #pragma unroll 4
    for (int k = 0; k < 32; k++) {
        int t = l + 32 * k;
        int mk = isbool ? (int)mask[(size_t)b * SS + t]
                        : ((const int*)mask)[(size_t)b * SS + t];
        int tg = tgT[t];
        if (t == 0) {
            num += startT[tg] + embT[tg];
        } else {
            int tgm = tgT[t - 1];
            float cval = trans[tgm * TT + tg] + embT[t * TT + tg];
            num += mk ? cval : 0.f;
        }
        cnt += mk ? 1 : 0;
    }
    #pragma unroll
    for (int o = 16; o; o >>= 1) {
        num += __shfl_xor_sync(FULL, num, o);
        cnt += __shfl_xor_sync(FULL, cnt, o);
    }
    int len = cnt;
    if (len < 1) len = 1;
    if (len > SS) len = SS;
    num += endT[tgT[len - 1]];           // uniform across lanes

    // ===== this lane's two output columns =====
    int jA = l;
    int jB = 32 + (l & 15);

    // ===== E = exp(transitions) columns in registers (f32x2 pairs) =====
    unsigned long long colA[24], colB[24];
    #pragma unroll
    for (int m = 0; m < 24; m++) {
        colA[m] = pk2(__expf(trans[(2 * m) * TT + jA]),
                      __expf(trans[(2 * m + 1) * TT + jA]));
        colB[m] = pk2(__expf(trans[(2 * m) * TT + jB]),
                      __expf(trans[(2 * m + 1) * TT + jB]));
    }

    // ===== init p0 = exp(start + emit0 - shift) =====
    float sA0 = startT[jA] + embT[jA];
    float sB0 = startT[jB] + embT[jB];
    float shift = __shfl_sync(FULL, sA0, 0);
    sP[w][0][l] = __expf(sA0 - shift);
    if (l < 16) sP[w][0][32 + l] = __expf(sB0 - shift);
    __syncwarp();

    // ===== emission prefetch ring (depth 4); row r at slot (r-1)&3 =====
    float bufA[4], bufB[4];
    #pragma unroll
    for (int u = 0; u < 4; u++) {
        bufA[u] = embT[(1 + u) * TT + jA];
        bufB[u] = embT[(1 + u) * TT + jB];
    }

    int ksum = 0;

    // ---- one recurrence step (branchless; RESC is a literal 0/1) ----
    #define CRF_STEP(t, idx, RESC)                                             \
    {                                                                          \
        float wA = __expf(bufA[idx]);                                          \
        float wB = __expf(bufB[idx]);                                          \
        int tp = (t) + 4; if (tp > SS - 1) tp = SS - 1;                        \
        bufA[idx] = embT[tp * TT + jA];                                        \
        bufB[idx] = embT[tp * TT + jB];                                        \
        int rb = ((t) + 1) & 1, wb = (t) & 1;                                  \
        const ulonglong2* sp =                                                 \
            reinterpret_cast<const ulonglong2*>(&sP[w][rb][0]);                \
        ulonglong2 v0 = sp[0];                                                 \
        if (RESC) {                                                            \
            float p00, p01;                                                    \
            upk2(v0.x, p00, p01);                                              \
            unsigned eb = (__float_as_uint(p00) >> 23) & 255u;                 \
            if (eb < 64u) eb = 64u;                                            \
            if (eb > 190u) eb = 190u;                                          \
            int kk = (int)eb - 127;                                            \
            float Mf = __uint_as_float((unsigned)(127 - kk) << 23);            \
            ksum += kk;                                                        \
            wA *= Mf; wB *= Mf;                                                \
        }                                                                      \
        unsigned long long a0 = 0, a1 = 0, c0 = 0, c1 = 0;                     \
        a0 = fma2(v0.x, colA[0], a0);                                          \
        c0 = fma2(v0.x, colB[0], c0);                                          \
        a1 = fma2(v0.y, colA[1], a1);                                          \
        c1 = fma2(v0.y, colB[1], c1);                                          \
        _Pragma("unroll")                                                      \
        for (int q = 1; q < 12; q++) {                                         \
            ulonglong2 v = sp[q];                                              \
            a0 = fma2(v.x, colA[2 * q], a0);                                   \
            c0 = fma2(v.x, colB[2 * q], c0);                                   \
            a1 = fma2(v.y, colA[2 * q + 1], a1);                               \
            c1 = fma2(v.y, colB[2 * q + 1], c1);                               \
        }                                                                      \
        float xA, yA, xB, yB;                                                  \
        upk2(add2(a0, a1), xA, yA);                                            \
        upk2(add2(c0, c1), xB, yB);                                            \
        float pA = (xA + yA) * wA;                                             \
        float pB = (xB + yB) * wB;                                             \
        sP[w][wb][l] = pA;                                                     \
        if (l < 16) sP[w][wb][32 + l] = pB;                                    \
        __syncwarp();                                                          \
    }

    int t = 1;
    // full quads: rescale at quad head only
    for (; t + 3 < len; t += 4) {
        CRF_STEP(t + 0, 0, 1)
        CRF_STEP(t + 1, 1, 0)
        CRF_STEP(t + 2, 2, 0)
        CRF_STEP(t + 3, 3, 0)
    }
    // remainder (0-3 steps): rescale every step (always safe)
    for (; t < len; t++) {
        int idx = (t - 1) & 3;
        CRF_STEP(t, idx, 1)
    }
    #undef CRF_STEP

    // ===== finalize: logZ = log(sum_j p_j e^{end_j}) + shift + ksum*ln2 =====
    int fb = (len - 1) & 1;
    float fin = sP[w][fb][jA] * __expf(endT[jA]);
    if (l < 16) fin += sP[w][fb][jB] * __expf(endT[jB]);
    #pragma unroll
    for (int o = 16; o; o >>= 1) fin += __shfl_xor_sync(FULL, fin, o);
    if (l == 0) {
        float logZ = __logf(fin) + shift + (float)ksum * 0.69314718055994531f;
        g_partial[b] = logZ - num;
    }

    // ===== last-CTA fused mean (deterministic fixed-order reduction) =====
    __syncthreads();
    if (tid == 0) {
        __threadfence();
        int prev = atomicAdd(&g_ctr, 1);
        sLast = (prev == gridDim.x - 1) ? 1 : 0;
    }
    __syncthreads();
    if (sLast) {
        __threadfence();
        float acc = 0.f;
        #pragma unroll
        for (int k = 0; k < 4; k++)
            acc += __ldcg(&g_partial[tid * 4 + k]);   // fixed order per thread
        sRed[tid] = acc;
        __syncthreads();
        #pragma unroll
        for (int o = 64; o > 0; o >>= 1) {
            if (tid < o) sRed[tid] += sRed[tid + o];  // fixed tree order
            __syncthreads();
        }
        if (tid == 0) {
            out[0] = sRed[0] * (1.0f / (float)BB);
            g_ctr = 0;                                // reset for next replay
        }
    }
}

extern "C" void kernel_launch(void* const* d_in, const int* in_sizes, int n_in,
                              void* d_out, int out_size) {
    const float*         em   = (const float*)d_in[0];
    const int*           tags = (const int*)d_in[1];
    const unsigned char* mask = (const unsigned char*)d_in[2];
    const float*         st   = (const float*)d_in[3];
    const float*         en   = (const float*)d_in[4];
    const float*         tr   = (const float*)d_in[5];
    crf_main<<<BB / 4, 128>>>(em, tags, mask, st, en, tr, (float*)d_out);
}